// round 3
// baseline (speedup 1.0000x reference)
#include <cuda_runtime.h>
#include <cstdint>

// Problem dims
#define BB    2048
#define TT    200
#define INF   1024
#define H1    2048
#define H2    1024
#define EMBED 1025   // H2 + 1 bias column

// Scratch (device globals; no allocation allowed)
__device__ float g_h1[(size_t)BB * H1];      // 16 MB
__device__ float g_h2[(size_t)BB * H2];      // 8 MB
__device__ float g_partials[BB];

// ---------------------------------------------------------------------------
// SGEMM body: C[M,N] = relu(A[M,K] @ B[K,N] + bias[N]), row-major fp32.
// 128x128 block tile, BK=8, 8x8 per thread, 256 threads.
// Requires M,N % 128 == 0, K % 8 == 0.
// ---------------------------------------------------------------------------
__device__ __forceinline__
void sgemm_body(const float* __restrict__ A, const float* __restrict__ B,
                const float* __restrict__ bias, float* __restrict__ C,
                int M, int N, int K)
{
    const int BK = 8, TM = 8, TN = 8;
    __shared__ float As[8][128];
    __shared__ float Bs[8][128];

    const int tid  = threadIdx.x;
    const int col0 = blockIdx.x * 128;
    const int row0 = blockIdx.y * 128;

    const int tx = tid % 16;  // 0..15
    const int ty = tid / 16;  // 0..15

    // global load indices
    const int aRow = tid >> 1;             // 0..127
    const int aCol = (tid & 1) * 4;        // 0 or 4
    const int bRow = tid >> 5;             // 0..7
    const int bCol = (tid & 31) * 4;       // 0..124

    const float* Ap = A + (size_t)(row0 + aRow) * K + aCol;
    const float* Bp = B + (size_t)bRow * N + col0 + bCol;

    float acc[TM][TN];
#pragma unroll
    for (int i = 0; i < TM; i++)
#pragma unroll
        for (int j = 0; j < TN; j++) acc[i][j] = 0.f;

    for (int k0 = 0; k0 < K; k0 += BK) {
        float4 av = *(const float4*)(Ap + k0);
        As[aCol + 0][aRow] = av.x;
        As[aCol + 1][aRow] = av.y;
        As[aCol + 2][aRow] = av.z;
        As[aCol + 3][aRow] = av.w;
        float4 bv = *(const float4*)(Bp + (size_t)k0 * N);
        *(float4*)&Bs[bRow][bCol] = bv;
        __syncthreads();

#pragma unroll
        for (int kk = 0; kk < BK; kk++) {
            float ar[TM], br[TN];
#pragma unroll
            for (int i = 0; i < TM; i += 4)
                *(float4*)&ar[i] = *(const float4*)&As[kk][ty * TM + i];
#pragma unroll
            for (int j = 0; j < TN; j += 4)
                *(float4*)&br[j] = *(const float4*)&Bs[kk][tx * TN + j];
#pragma unroll
            for (int i = 0; i < TM; i++)
#pragma unroll
                for (int j = 0; j < TN; j++)
                    acc[i][j] += ar[i] * br[j];
        }
        __syncthreads();
    }

#pragma unroll
    for (int i = 0; i < TM; i++) {
        const int r = row0 + ty * TM + i;
#pragma unroll
        for (int j = 0; j < TN; j += 4) {
            const int c = col0 + tx * TN + j;
            float4 v;
            v.x = fmaxf(acc[i][j + 0] + bias[c + 0], 0.f);
            v.y = fmaxf(acc[i][j + 1] + bias[c + 1], 0.f);
            v.z = fmaxf(acc[i][j + 2] + bias[c + 2], 0.f);
            v.w = fmaxf(acc[i][j + 3] + bias[c + 3], 0.f);
            *(float4*)&C[(size_t)r * N + c] = v;
        }
    }
}

// Thin wrappers so scratch globals are referenced from device code only.
__global__ __launch_bounds__(256, 2)
void gemm1_kernel(const float* __restrict__ x, const float* __restrict__ W1,
                  const float* __restrict__ b1)
{
    sgemm_body(x, W1, b1, g_h1, BB, H1, INF);
}

__global__ __launch_bounds__(256, 2)
void gemm2_kernel(const float* __restrict__ W2, const float* __restrict__ b2)
{
    sgemm_body(g_h1, W2, b2, g_h2, BB, H2, H1);
}

// ---------------------------------------------------------------------------
// Gather + dot + BCE + sigmoid. One block per batch row b.
// h2[b] (1024 f32) staged in SMEM, reused across T=200 targets.
// logits[b,t] = sum_d emb[id][d]*h2[b][d] + emb[id][1024]  (bias column trick)
// NOTE: emb rows have stride 1025 floats (4100 B) -> only 4-byte aligned.
// All emb accesses MUST be scalar LDG.32 (float4 traps: misaligned address).
// id==0 -> zero embedding row -> z=0 exactly.
// probs == nullptr -> dump probs into g_h1 scratch (loss-only output layout).
// ---------------------------------------------------------------------------
__global__ __launch_bounds__(256)
void gather_bce_kernel(const float* __restrict__ emb,
                       const int*   __restrict__ ids,
                       const float* __restrict__ tv,
                       const float* __restrict__ tm,
                       float* __restrict__ probs)
{
    __shared__ float hs[H2];
    __shared__ float warp_part[8];

    if (probs == nullptr) probs = g_h1;

    const int b    = blockIdx.x;
    const int tid  = threadIdx.x;
    const int lane = tid & 31;
    const int w    = tid >> 5;

    // stage h2 row: 256 threads x float4 = 1024 floats (aligned, SMEM dst)
    ((float4*)hs)[tid] = ((const float4*)(g_h2 + (size_t)b * H2))[tid];
    __syncthreads();

    float part = 0.f;
    for (int t = w; t < TT; t += 8) {
        const int id = ids[b * TT + t];
        float z = 0.f;
        if (id != 0) {
            const float* er = emb + (size_t)id * EMBED;
            float acc = 0.f;
            // scalar loads only (4-byte alignment); coalesced across lanes
#pragma unroll
            for (int i = 0; i < 32; i++)
                acc = fmaf(__ldg(er + lane + i * 32), hs[lane + i * 32], acc);
#pragma unroll
            for (int o = 16; o; o >>= 1)
                acc += __shfl_xor_sync(0xffffffffu, acc, o);
            z = acc + __ldg(er + 1024);
        }
        if (lane == 0) {
            const float y = tv[b * TT + t];
            const float m = tm[b * TT + t];
            const float bce = fmaxf(z, 0.f) - z * y + log1pf(expf(-fabsf(z)));
            part += m * bce;
            probs[b * TT + t] = 1.f / (1.f + expf(-z));
        }
    }
    if (lane == 0) warp_part[w] = part;
    __syncthreads();
    if (tid == 0) {
        float s = 0.f;
#pragma unroll
        for (int i = 0; i < 8; i++) s += warp_part[i];
        g_partials[b] = s;
    }
}

// Deterministic final reduction: fixed-order tree over 2048 partials.
__global__ __launch_bounds__(256)
void finalize_loss(float* __restrict__ out)
{
    __shared__ float s[256];
    float acc = 0.f;
    for (int i = threadIdx.x; i < BB; i += 256) acc += g_partials[i];
    s[threadIdx.x] = acc;
    __syncthreads();
    for (int o = 128; o; o >>= 1) {
        if (threadIdx.x < o) s[threadIdx.x] += s[threadIdx.x + o];
        __syncthreads();
    }
    if (threadIdx.x == 0) out[0] = s[0] / (float)((size_t)BB * TT);
}

// ---------------------------------------------------------------------------
extern "C" void kernel_launch(void* const* d_in, const int* in_sizes, int n_in,
                              void* d_out, int out_size)
{
    const float* x   = (const float*)d_in[0];
    const float* W1  = (const float*)d_in[1];
    const float* b1  = (const float*)d_in[2];
    const float* W2  = (const float*)d_in[3];
    const float* b2  = (const float*)d_in[4];
    const float* emb = (const float*)d_in[5];
    const int*   ids = (const int*)  d_in[6];
    const float* tv  = (const float*)d_in[7];
    const float* tm  = (const float*)d_in[8];
    float* out = (float*)d_out;

    // GEMM1: [2048,1024] @ [1024,2048] -> g_h1
    {
        dim3 grid(H1 / 128, BB / 128);
        gemm1_kernel<<<grid, 256>>>(x, W1, b1);
    }
    // GEMM2: [2048,2048] @ [2048,1024] -> g_h2
    {
        dim3 grid(H2 / 128, BB / 128);
        gemm2_kernel<<<grid, 256>>>(W2, b2);
    }

    const int nBT = BB * TT;

    // Output layout handling:
    //   out_size >= nBT+1 : [loss, probs...]   (expected)
    //   out_size == nBT   : probs only
    //   else              : loss only (probs to scratch)
    float* probs      = nullptr;   // nullptr -> scratch inside kernel
    float* loss_dst   = nullptr;
    if (out_size >= nBT + 1)      { loss_dst = out; probs = out + 1; }
    else if (out_size == nBT)     { probs = out; }
    else                          { loss_dst = out; }

    gather_bce_kernel<<<BB, 256>>>(emb, ids, tv, tm, probs);

    if (loss_dst != nullptr) {
        finalize_loss<<<1, 256>>>(loss_dst);
    }
}

// round 4
// speedup vs baseline: 1.6571x; 1.6571x over previous
#include <cuda_runtime.h>
#include <cuda_bf16.h>
#include <cstdint>

// Problem dims
#define BB    2048
#define TT    200
#define INF   1024
#define H1    2048
#define H2    1024
#define EMBED 1025   // H2 + 1 bias column

// Scratch (device globals; no allocation allowed)
__device__ float g_h1[(size_t)BB * H1];      // 16 MB
__device__ float g_h2[(size_t)BB * H2];      // 8 MB
__device__ float g_partials[BB];

// ---------------------------------------------------------------------------
// Split-bf16 tensor-core GEMM: C = relu(A@B + bias), fp32 in/out.
// a = ah + al (bf16 hi + bf16 residual); C ≈ ah*bh + ah*bl + al*bh (3 MMAs),
// fp32 accumulate. Dropped al*bl term ~2^-16 relative.
// CTA tile 128x128x32, 256 threads = 8 warps (2x4), warp tile 64x32,
// mma.sync.aligned.m16n8k16.row.col.f32.bf16.bf16.f32.
// ---------------------------------------------------------------------------
#define SA 40    // A smem row stride (bf16 units), 128 rows   -> conflict-free frag loads
#define SB 136   // B smem row stride (bf16 units), 32 k-rows  -> conflict-free u16 loads

__device__ __forceinline__ void bf16_split(float v, unsigned short& h, unsigned short& l)
{
    __nv_bfloat16 bh = __float2bfloat16(v);
    float r = v - __bfloat162float(bh);
    __nv_bfloat16 bl = __float2bfloat16(r);
    h = reinterpret_cast<unsigned short&>(bh);
    l = reinterpret_cast<unsigned short&>(bl);
}

__device__ __forceinline__ void mma16816(float* c, const unsigned* a, unsigned b0, unsigned b1)
{
    asm volatile(
        "mma.sync.aligned.m16n8k16.row.col.f32.bf16.bf16.f32 "
        "{%0,%1,%2,%3},{%4,%5,%6,%7},{%8,%9},{%0,%1,%2,%3};\n"
        : "+f"(c[0]), "+f"(c[1]), "+f"(c[2]), "+f"(c[3])
        : "r"(a[0]), "r"(a[1]), "r"(a[2]), "r"(a[3]), "r"(b0), "r"(b1));
}

__device__ __forceinline__
void gemm_tc_body(const float* __restrict__ A, const float* __restrict__ B,
                  const float* __restrict__ bias, float* __restrict__ C,
                  int N, int K)
{
    __shared__ unsigned short Ash[128 * SA];
    __shared__ unsigned short Asl[128 * SA];
    __shared__ unsigned short Bsh[32 * SB];
    __shared__ unsigned short Bsl[32 * SB];

    const int tid  = threadIdx.x;
    const int lane = tid & 31;
    const int warp = tid >> 5;
    const int wm   = warp >> 2;      // 0..1
    const int wn   = warp & 3;       // 0..3
    const int grp  = lane >> 2;      // 0..7
    const int tg   = lane & 3;       // 0..3

    const int col0 = blockIdx.x * 128;
    const int row0 = blockIdx.y * 128;

    // loader index precompute (4 float4 per thread per operand)
    int aRow[4], aK[4], bK[4], bN[4];
#pragma unroll
    for (int i = 0; i < 4; i++) {
        int idx = tid + i * 256;
        aRow[i] = idx >> 3;        aK[i] = (idx & 7) * 4;    // A: 128 x 32
        bK[i]   = idx >> 5;        bN[i] = (idx & 31) * 4;   // B: 32 x 128
    }

    float acc[4][4][4];
#pragma unroll
    for (int mt = 0; mt < 4; mt++)
#pragma unroll
        for (int nt = 0; nt < 4; nt++)
#pragma unroll
            for (int q = 0; q < 4; q++) acc[mt][nt][q] = 0.f;

    float4 pa[4], pb[4];
    // prefetch k-tile 0
#pragma unroll
    for (int i = 0; i < 4; i++) {
        pa[i] = *(const float4*)(A + (size_t)(row0 + aRow[i]) * K + aK[i]);
        pb[i] = *(const float4*)(B + (size_t)bK[i] * N + col0 + bN[i]);
    }

    const int NITER = K / 32;
    for (int it = 0; it < NITER; ++it) {
        // convert + store current k-tile to SMEM
#pragma unroll
        for (int i = 0; i < 4; i++) {
            unsigned short h0, l0, h1, l1, h2, l2, h3, l3;
            bf16_split(pa[i].x, h0, l0); bf16_split(pa[i].y, h1, l1);
            bf16_split(pa[i].z, h2, l2); bf16_split(pa[i].w, h3, l3);
            int ba = aRow[i] * SA + aK[i];
            *(unsigned*)&Ash[ba]     = (unsigned)h0 | ((unsigned)h1 << 16);
            *(unsigned*)&Ash[ba + 2] = (unsigned)h2 | ((unsigned)h3 << 16);
            *(unsigned*)&Asl[ba]     = (unsigned)l0 | ((unsigned)l1 << 16);
            *(unsigned*)&Asl[ba + 2] = (unsigned)l2 | ((unsigned)l3 << 16);

            bf16_split(pb[i].x, h0, l0); bf16_split(pb[i].y, h1, l1);
            bf16_split(pb[i].z, h2, l2); bf16_split(pb[i].w, h3, l3);
            int bb = bK[i] * SB + bN[i];
            *(unsigned*)&Bsh[bb]     = (unsigned)h0 | ((unsigned)h1 << 16);
            *(unsigned*)&Bsh[bb + 2] = (unsigned)h2 | ((unsigned)h3 << 16);
            *(unsigned*)&Bsl[bb]     = (unsigned)l0 | ((unsigned)l1 << 16);
            *(unsigned*)&Bsl[bb + 2] = (unsigned)l2 | ((unsigned)l3 << 16);
        }
        __syncthreads();

        // prefetch next k-tile into registers (hides gmem latency behind MMAs)
        if (it + 1 < NITER) {
            const int k0n = (it + 1) * 32;
#pragma unroll
            for (int i = 0; i < 4; i++) {
                pa[i] = *(const float4*)(A + (size_t)(row0 + aRow[i]) * K + k0n + aK[i]);
                pb[i] = *(const float4*)(B + (size_t)(k0n + bK[i]) * N + col0 + bN[i]);
            }
        }

        // compute: 2 k-steps of 16
#pragma unroll
        for (int ks = 0; ks < 2; ks++) {
            const int k0 = ks * 16;
            unsigned ah[4][4], al[4][4];
#pragma unroll
            for (int mt = 0; mt < 4; mt++) {
                int r = (wm * 64 + mt * 16 + grp) * SA + k0 + 2 * tg;
                ah[mt][0] = *(const unsigned*)&Ash[r];
                ah[mt][1] = *(const unsigned*)&Ash[r + 8 * SA];
                ah[mt][2] = *(const unsigned*)&Ash[r + 8];
                ah[mt][3] = *(const unsigned*)&Ash[r + 8 * SA + 8];
                al[mt][0] = *(const unsigned*)&Asl[r];
                al[mt][1] = *(const unsigned*)&Asl[r + 8 * SA];
                al[mt][2] = *(const unsigned*)&Asl[r + 8];
                al[mt][3] = *(const unsigned*)&Asl[r + 8 * SA + 8];
            }
#pragma unroll
            for (int nt = 0; nt < 4; nt++) {
                const int n  = wn * 32 + nt * 8 + grp;
                const int kb = k0 + 2 * tg;
                unsigned bh0 = (unsigned)Bsh[kb * SB + n]       | ((unsigned)Bsh[(kb + 1) * SB + n] << 16);
                unsigned bh1 = (unsigned)Bsh[(kb + 8) * SB + n] | ((unsigned)Bsh[(kb + 9) * SB + n] << 16);
                unsigned bl0 = (unsigned)Bsl[kb * SB + n]       | ((unsigned)Bsl[(kb + 1) * SB + n] << 16);
                unsigned bl1 = (unsigned)Bsl[(kb + 8) * SB + n] | ((unsigned)Bsl[(kb + 9) * SB + n] << 16);
#pragma unroll
                for (int mt = 0; mt < 4; mt++) {
                    mma16816(acc[mt][nt], ah[mt], bh0, bh1);  // hi*hi
                    mma16816(acc[mt][nt], ah[mt], bl0, bl1);  // hi*lo
                    mma16816(acc[mt][nt], al[mt], bh0, bh1);  // lo*hi
                }
            }
        }
        __syncthreads();
    }

    // epilogue: bias + relu, float2 stores
#pragma unroll
    for (int mt = 0; mt < 4; mt++) {
        const int r = row0 + wm * 64 + mt * 16 + grp;
#pragma unroll
        for (int nt = 0; nt < 4; nt++) {
            const int c = col0 + wn * 32 + nt * 8 + 2 * tg;
            const float2 bv = *(const float2*)(bias + c);
            float2 o;
            o.x = fmaxf(acc[mt][nt][0] + bv.x, 0.f);
            o.y = fmaxf(acc[mt][nt][1] + bv.y, 0.f);
            *(float2*)&C[(size_t)r * N + c] = o;
            o.x = fmaxf(acc[mt][nt][2] + bv.x, 0.f);
            o.y = fmaxf(acc[mt][nt][3] + bv.y, 0.f);
            *(float2*)&C[(size_t)(r + 8) * N + c] = o;
        }
    }
}

__global__ __launch_bounds__(256, 1)
void gemm1_kernel(const float* __restrict__ x, const float* __restrict__ W1,
                  const float* __restrict__ b1)
{
    gemm_tc_body(x, W1, b1, g_h1, H1, INF);
}

__global__ __launch_bounds__(256, 1)
void gemm2_kernel(const float* __restrict__ W2, const float* __restrict__ b2)
{
    gemm_tc_body(g_h1, W2, b2, g_h2, H2, H1);
}

// ---------------------------------------------------------------------------
// Gather + dot + BCE + sigmoid. One block per batch row b. (unchanged, passing)
// emb rows are 4-byte aligned only (stride 1025 floats) -> scalar LDG.32 only.
// ---------------------------------------------------------------------------
__global__ __launch_bounds__(256)
void gather_bce_kernel(const float* __restrict__ emb,
                       const int*   __restrict__ ids,
                       const float* __restrict__ tv,
                       const float* __restrict__ tm,
                       float* __restrict__ probs)
{
    __shared__ float hs[H2];
    __shared__ float warp_part[8];

    if (probs == nullptr) probs = g_h1;

    const int b    = blockIdx.x;
    const int tid  = threadIdx.x;
    const int lane = tid & 31;
    const int w    = tid >> 5;

    ((float4*)hs)[tid] = ((const float4*)(g_h2 + (size_t)b * H2))[tid];
    __syncthreads();

    float part = 0.f;
    for (int t = w; t < TT; t += 8) {
        const int id = ids[b * TT + t];
        float z = 0.f;
        if (id != 0) {
            const float* er = emb + (size_t)id * EMBED;
            float acc = 0.f;
#pragma unroll
            for (int i = 0; i < 32; i++)
                acc = fmaf(__ldg(er + lane + i * 32), hs[lane + i * 32], acc);
#pragma unroll
            for (int o = 16; o; o >>= 1)
                acc += __shfl_xor_sync(0xffffffffu, acc, o);
            z = acc + __ldg(er + 1024);
        }
        if (lane == 0) {
            const float y = tv[b * TT + t];
            const float m = tm[b * TT + t];
            const float bce = fmaxf(z, 0.f) - z * y + log1pf(expf(-fabsf(z)));
            part += m * bce;
            probs[b * TT + t] = 1.f / (1.f + expf(-z));
        }
    }
    if (lane == 0) warp_part[w] = part;
    __syncthreads();
    if (tid == 0) {
        float s = 0.f;
#pragma unroll
        for (int i = 0; i < 8; i++) s += warp_part[i];
        g_partials[b] = s;
    }
}

// Deterministic final reduction.
__global__ __launch_bounds__(256)
void finalize_loss(float* __restrict__ out)
{
    __shared__ float s[256];
    float acc = 0.f;
    for (int i = threadIdx.x; i < BB; i += 256) acc += g_partials[i];
    s[threadIdx.x] = acc;
    __syncthreads();
    for (int o = 128; o; o >>= 1) {
        if (threadIdx.x < o) s[threadIdx.x] += s[threadIdx.x + o];
        __syncthreads();
    }
    if (threadIdx.x == 0) out[0] = s[0] / (float)((size_t)BB * TT);
}

// ---------------------------------------------------------------------------
extern "C" void kernel_launch(void* const* d_in, const int* in_sizes, int n_in,
                              void* d_out, int out_size)
{
    const float* x   = (const float*)d_in[0];
    const float* W1  = (const float*)d_in[1];
    const float* b1  = (const float*)d_in[2];
    const float* W2  = (const float*)d_in[3];
    const float* b2  = (const float*)d_in[4];
    const float* emb = (const float*)d_in[5];
    const int*   ids = (const int*)  d_in[6];
    const float* tv  = (const float*)d_in[7];
    const float* tm  = (const float*)d_in[8];
    float* out = (float*)d_out;

    // GEMM1: [2048,1024] @ [1024,2048] -> g_h1
    {
        dim3 grid(H1 / 128, BB / 128);
        gemm1_kernel<<<grid, 256>>>(x, W1, b1);
    }
    // GEMM2: [2048,2048] @ [2048,1024] -> g_h2
    {
        dim3 grid(H2 / 128, BB / 128);
        gemm2_kernel<<<grid, 256>>>(W2, b2);
    }

    const int nBT = BB * TT;
    float* probs    = nullptr;   // nullptr -> scratch inside kernel
    float* loss_dst = nullptr;
    if (out_size >= nBT + 1)      { loss_dst = out; probs = out + 1; }
    else if (out_size == nBT)     { probs = out; }
    else                          { loss_dst = out; }

    gather_bce_kernel<<<BB, 256>>>(emb, ids, tv, tm, probs);

    if (loss_dst != nullptr) {
        finalize_loss<<<1, 256>>>(loss_dst);
    }
}